// round 13
// baseline (speedup 1.0000x reference)
#include <cuda_runtime.h>
#include <cuda_fp16.h>

#define NMAX 100000
#define EMAX 1600000
#define H    64
#define FIN  16
#define EDIM 9
#define CAP  64          // per-node bucket capacity (P(deg>64) ~ 1e-33)
#define QS   8192.0f     // fixed-point scale for a_edge (range +-2, step 1.2e-4)

// ---------------- scratch (static __device__, no allocations) ----------------
__device__ __half2 g_h2[NMAX * 32];        // h after x@W, half2: lane owns dims 2l,2l+1
__device__ float    g_asrc[NMAX];
__device__ float    g_adst[NMAX];
__device__ float    g_y[NMAX];             // relu(out_nodes) @ lin_w per node
__device__ int      g_cnt[NMAX];           // bucket cursors / degrees
__device__ unsigned g_bucket[NMAX * CAP];  // packed (src:17 | biased-q15 a_edge)
__device__ float    g_we[EDIM];            // W_edge @ att_edge
__device__ __align__(16) float g_ws[FIN];  // W @ att_src
__device__ __align__(16) float g_wd[FIN];  // W @ att_dst
__device__ int      g_idx64;               // 1 if edge_index is int64, 0 if int32

// ---------------- fused setup: zero cnt + dtype probe + weight precompute -----
__global__ void k_setup(const float* __restrict__ W, const float* __restrict__ We,
                        const float* __restrict__ as_, const float* __restrict__ ad_,
                        const float* __restrict__ ae_, const int* __restrict__ ei32, int n) {
    int i = blockIdx.x * 256 + threadIdx.x;
    if (i < n) g_cnt[i] = 0;
    if (blockIdx.x == 0) {
        // dtype probe: int64 edge_index has zero high words (first 8KB, in-bounds either way)
        int tid = threadIdx.x, nz = 0;
        #pragma unroll
        for (int j = 0; j < 4; j++) {
            int k = tid * 4 + j;                 // 0..1023
            if (ei32[2 * k + 1] != 0) nz = 1;
        }
        int any = __syncthreads_or(nz);
        if (tid == 0) g_idx64 = any ? 0 : 1;
    } else if (blockIdx.x == 1) {
        // precompute ws = W@att_src, wd = W@att_dst, we = We@att_e
        int w = threadIdx.x >> 5, lane = threadIdx.x & 31;   // 8 warps
        float ae0 = ae_[lane], ae1 = ae_[lane + 32];
        float as0 = as_[lane], as1 = as_[lane + 32];
        float ad0 = ad_[lane], ad1 = ad_[lane + 32];
        for (int r = w; r < FIN; r += 8) {
            float ps = W[r * H + lane] * as0 + W[r * H + lane + 32] * as1;
            float pd = W[r * H + lane] * ad0 + W[r * H + lane + 32] * ad1;
            #pragma unroll
            for (int o = 16; o; o >>= 1) {
                ps += __shfl_down_sync(0xffffffffu, ps, o);
                pd += __shfl_down_sync(0xffffffffu, pd, o);
            }
            if (!lane) { g_ws[r] = ps; g_wd[r] = pd; }
        }
        for (int r = w; r < EDIM; r += 8) {
            float p = We[r * H + lane] * ae0 + We[r * H + lane + 32] * ae1;
            #pragma unroll
            for (int o = 16; o; o >>= 1) p += __shfl_down_sync(0xffffffffu, p, o);
            if (!lane) g_we[r] = p;
        }
    }
}

// ------- fused main: edge blocks (a_edge + bucket scatter) || node blocks (h) --
#define EPB 512          // edges per edge-block (2 per thread)
#define NPW 16
__global__ __launch_bounds__(256, 5) void k_main(
    const float* __restrict__ x, const float* __restrict__ W,
    const void* __restrict__ ei_raw, const float* __restrict__ ea,
    int n, int E, int edgeBlocks) {
    __shared__ float swe[EDIM];
    __shared__ __align__(16) float sea[EPB * EDIM];   // 16B-aligned for float4 staging
    if (blockIdx.x < edgeBlocks) {
        // ---- edge part: 2 edges/thread, a = ea @ w_e, one-atomic packed scatter
        int tid = threadIdx.x;
        if (tid < EDIM) swe[tid] = g_we[tid];
        long long base = (long long)blockIdx.x * EPB;
        long long astart = base * EDIM;
        long long total = (long long)E * EDIM;
        // global offset astart*4 bytes = blockIdx*18432 -> 16B multiple when ea is 16B aligned
        if (astart + (long long)(EPB * EDIM) <= total &&
            ((((unsigned long long)(ea)) & 15ull) == 0ull)) {
            const float4* srcv = (const float4*)(ea + astart);
            float4* dstv = (float4*)sea;
            #pragma unroll
            for (int i = 0; i < (EPB * EDIM) / 4 / 256; i++)    // 4 iters
                dstv[tid + i * 256] = srcv[tid + i * 256];
            {   // remainder (1152 = 4*256 + 128)
                int i = (EPB * EDIM) / 4 / 256 * 256 + tid;
                if (i < (EPB * EDIM) / 4) dstv[i] = srcv[i];
            }
        } else {
            int acount = (int)min((long long)(EPB * EDIM), total - astart);
            for (int i = tid; i < acount; i += 256) sea[i] = ea[astart + i];
        }
        __syncthreads();
        int e0 = (int)base + tid;
        int e1 = e0 + 256;
        bool v0 = e0 < E, v1 = e1 < E;
        int s0 = 0, d0 = 0, s1 = 0, d1 = 0;
        if (g_idx64) {
            const long long* ei = (const long long*)ei_raw;
            if (v0) { s0 = (int)__ldg(&ei[e0]); d0 = (int)__ldg(&ei[E + e0]); }
            if (v1) { s1 = (int)__ldg(&ei[e1]); d1 = (int)__ldg(&ei[E + e1]); }
        } else {
            const int* ei = (const int*)ei_raw;
            if (v0) { s0 = __ldg(&ei[e0]); d0 = __ldg(&ei[E + e0]); }
            if (v1) { s1 = __ldg(&ei[e1]); d1 = __ldg(&ei[E + e1]); }
        }
        float a0 = 0.f, a1 = 0.f;
        #pragma unroll
        for (int k = 0; k < EDIM; k++) {
            a0 = fmaf(sea[tid * EDIM + k], swe[k], a0);
            a1 = fmaf(sea[(tid + 256) * EDIM + k], swe[k], a1);
        }
        int q0 = max(-16383, min(16383, __float2int_rn(a0 * QS)));
        int q1 = max(-16383, min(16383, __float2int_rn(a1 * QS)));
        // two independent atomic->store chains, interleaved for MLP
        int p0 = -1, p1 = -1;
        if (v0) p0 = atomicAdd(&g_cnt[d0], 1);
        if (v1) p1 = atomicAdd(&g_cnt[d1], 1);
        if (v0 && p0 < CAP)
            g_bucket[d0 * CAP + p0] = ((unsigned)s0 << 15) | (unsigned)(q0 + 16384);
        if (v1 && p1 < CAP)
            g_bucket[d1 * CAP + p1] = ((unsigned)s1 << 15) | (unsigned)(q1 + 16384);
    } else {
        // ---- node part: h = x@W (half2), a_src, a_dst ----
        int bid = blockIdx.x - edgeBlocks;
        int gw = bid * 8 + (threadIdx.x >> 5);
        int lane = threadIdx.x & 31;
        int base0 = gw * NPW;
        if (base0 >= n) return;
        float w0[FIN], w1[FIN];
        #pragma unroll
        for (int k = 0; k < FIN; k++) {
            float2 wv = ((const float2*)(W + k * H))[lane];
            w0[k] = wv.x; w1[k] = wv.y;
        }
        float4 ws4 = ((const float4*)g_ws)[lane & 3];
        float4 wd4 = ((const float4*)g_wd)[lane & 3];
        for (int b = 0; b < NPW; b += 8) {
            int base = base0 + b;
            if (base >= n) break;
            int mynode = base + (lane >> 2);
            float4 x4 = make_float4(0.f, 0.f, 0.f, 0.f);
            if (mynode < n) x4 = ((const float4*)x)[base * 4 + lane];
            float rs = x4.x * ws4.x + x4.y * ws4.y + x4.z * ws4.z + x4.w * ws4.w;
            float rd = x4.x * wd4.x + x4.y * wd4.y + x4.z * wd4.z + x4.w * wd4.w;
            rs += __shfl_xor_sync(0xffffffffu, rs, 1);
            rd += __shfl_xor_sync(0xffffffffu, rd, 1);
            rs += __shfl_xor_sync(0xffffffffu, rs, 2);
            rd += __shfl_xor_sync(0xffffffffu, rd, 2);
            if ((lane & 3) == 0 && mynode < n) { g_asrc[mynode] = rs; g_adst[mynode] = rd; }
            #pragma unroll
            for (int i = 0; i < 8; i++) {
                int node = base + i;
                if (node >= n) break;              // uniform across warp
                float a0 = 0.f, a1 = 0.f;
                #pragma unroll
                for (int k = 0; k < FIN; k++) {
                    float xc = ((k & 3) == 0) ? x4.x : ((k & 3) == 1) ? x4.y
                             : ((k & 3) == 2) ? x4.z : x4.w;
                    float xk = __shfl_sync(0xffffffffu, xc, (i << 2) + (k >> 2));
                    a0 = fmaf(xk, w0[k], a0);
                    a1 = fmaf(xk, w1[k], a1);
                }
                g_h2[node * 32 + lane] = __floats2half2_rn(a0, a1);
            }
        }
    }
}

// ------- per node warp: softmax + aggregate + relu + @lin_w (single pass) -----
__global__ void k_aggregate(const float* __restrict__ bias, const float* __restrict__ lin_w, int n) {
    int warp = threadIdx.x >> 5, lane = threadIdx.x & 31;
    int node = blockIdx.x * (blockDim.x >> 5) + warp;
    if (node >= n) return;
    int deg = g_cnt[node];
    int cnt = min(deg, CAP);
    float adst_n = g_adst[node];

    const unsigned* bkt = &g_bucket[node * CAP];
    float acc0 = 0.f, acc1 = 0.f;
    float asum = 0.f, dsum = 0.f;

    for (int i0 = 0; i0 < cnt; i0 += 32) {
        bool valid = (i0 + lane) < cnt;
        unsigned w = __ldg(&bkt[valid ? (i0 + lane) : 0]);   // coalesced 128B per warp
        int src = (int)(w >> 15);
        float a_l = ((int)(w & 0x7FFFu) - 16384) * (1.f / QS);
        float asrc_s = __ldg(&g_asrc[src]);                  // lane-parallel random gather
        float alf = asrc_s + adst_n + a_l;
        alf = (alf >= 0.f) ? alf : 0.2f * alf;               // leaky_relu(0.2)
        float ex = valid ? __expf(alf) : 0.f;
        asum += valid ? a_l : 0.f;
        dsum += ex;
        int m = min(cnt - i0, 32);
        #pragma unroll 8
        for (int j = 0; j < m; j++) {
            unsigned wj = __shfl_sync(0xffffffffu, w, j);
            float exj = __shfl_sync(0xffffffffu, ex, j);
            int sj = (int)(wj >> 15);
            float2 hf = __half22float2(g_h2[sj * 32 + lane]);
            acc0 = fmaf(exj, hf.x, acc0);
            acc1 = fmaf(exj, hf.y, acc1);
        }
    }
    #pragma unroll
    for (int o = 16; o; o >>= 1) {
        asum += __shfl_xor_sync(0xffffffffu, asum, o);
        dsum += __shfl_xor_sync(0xffffffffu, dsum, o);
    }
    // self loop: alpha = a_src + a_dst + mean(a_edge over incoming)
    float al = g_asrc[node] + adst_n + asum / fmaxf((float)deg, 1.f);
    al = (al >= 0.f) ? al : 0.2f * al;
    float exl = __expf(al);
    {
        float2 hf = __half22float2(g_h2[node * 32 + lane]);
        acc0 = fmaf(exl, hf.x, acc0);
        acc1 = fmaf(exl, hf.y, acc1);
    }
    float inv = 1.f / (dsum + exl + 1e-16f);
    float v0 = fmaxf(acc0 * inv + __ldg(&bias[2 * lane]),     0.f);
    float v1 = fmaxf(acc1 * inv + __ldg(&bias[2 * lane + 1]), 0.f);
    float yp = v0 * __ldg(&lin_w[2 * lane]) + v1 * __ldg(&lin_w[2 * lane + 1]);
    #pragma unroll
    for (int o = 16; o; o >>= 1) yp += __shfl_down_sync(0xffffffffu, yp, o);
    if (!lane) g_y[node] = yp;
}

// ---------------- per edge readout: 4 edges/thread, batched gathers -----------
#define OUT_Q 4
__global__ __launch_bounds__(512) void k_out(
    const void* __restrict__ ei_raw, float* __restrict__ out,
    const float* __restrict__ lin_b, int E, int stride) {
    int gid = blockIdx.x * 512 + threadIdx.x;
    float lb = __ldg(&lin_b[0]);
    int s[OUT_Q], d[OUT_Q];
    bool v[OUT_Q];
    // phase 1: coalesced index loads (independent)
    if (g_idx64) {
        const long long* ei = (const long long*)ei_raw;
        #pragma unroll
        for (int j = 0; j < OUT_Q; j++) {
            int e = gid + j * stride;
            v[j] = e < E;
            s[j] = v[j] ? (int)ei[e] : 0;
            d[j] = v[j] ? (int)ei[E + e] : 0;
        }
    } else {
        const int* ei = (const int*)ei_raw;
        #pragma unroll
        for (int j = 0; j < OUT_Q; j++) {
            int e = gid + j * stride;
            v[j] = e < E;
            s[j] = v[j] ? ei[e] : 0;
            d[j] = v[j] ? ei[E + e] : 0;
        }
    }
    // phase 2: independent random gathers in flight
    float ys[OUT_Q], yd[OUT_Q];
    #pragma unroll
    for (int j = 0; j < OUT_Q; j++) {
        ys[j] = __ldg(&g_y[s[j]]);
        yd[j] = __ldg(&g_y[d[j]]);
    }
    // phase 3: compute + coalesced stores
    #pragma unroll
    for (int j = 0; j < OUT_Q; j++) {
        if (v[j]) {
            float z = 0.5f * (ys[j] + yd[j]) + lb;
            out[gid + j * stride] = 1.f / (1.f + __expf(-z));
        }
    }
}

// ---------------- launch -------------------------------------------------------
extern "C" void kernel_launch(void* const* d_in, const int* in_sizes, int n_in,
                              void* d_out, int out_size) {
    const float* x       = (const float*)d_in[0];
    const float* ea      = (const float*)d_in[1];
    const float* W       = (const float*)d_in[2];
    const float* We      = (const float*)d_in[3];
    const float* att_src = (const float*)d_in[4];
    const float* att_dst = (const float*)d_in[5];
    const float* att_e   = (const float*)d_in[6];
    const float* bias    = (const float*)d_in[7];
    const float* lin_w   = (const float*)d_in[8];
    const float* lin_b   = (const float*)d_in[9];
    const void*  ei      = (const void*)d_in[10];

    int n = in_sizes[0] / FIN;       // 100000
    int E = in_sizes[10] / 2;        // 1600000 (element count, dtype-independent)

    k_setup<<<(n + 255) / 256, 256>>>(W, We, att_src, att_dst, att_e, (const int*)ei, n);

    int edgeBlocks = (E + EPB - 1) / EPB;                 // 3125
    int nodeBlocks = ((n + NPW - 1) / NPW + 7) / 8;       // 782
    k_main<<<edgeBlocks + nodeBlocks, 256>>>(x, W, ei, ea, n, E, edgeBlocks);

    k_aggregate<<<(n + 7) / 8, 256>>>(bias, lin_w, n);

    int outBlocks = (E + 512 * OUT_Q - 1) / (512 * OUT_Q);  // 782
    int stride = outBlocks * 512;
    k_out<<<outBlocks, 512>>>(ei, (float*)d_out, lin_b, E, stride);
}

// round 14
// speedup vs baseline: 1.0810x; 1.0810x over previous
#include <cuda_runtime.h>
#include <cuda_fp16.h>

#define NMAX 100000
#define EMAX 1600000
#define H    64
#define FIN  16
#define EDIM 9
#define CAP  64          // per-node bucket capacity (P(deg>64) ~ 1e-33)
#define QS   8192.0f     // fixed-point scale for a_edge (range +-2, step 1.2e-4)

// ---------------- scratch (static __device__, no allocations) ----------------
__device__ __half2 g_h2[NMAX * 32];        // h after x@W, half2: lane owns dims 2l,2l+1
__device__ float    g_asrc[NMAX];
__device__ float    g_adst[NMAX];
__device__ float    g_y[NMAX];             // relu(out_nodes) @ lin_w per node
__device__ int      g_cnt[NMAX];           // bucket cursors / degrees
__device__ unsigned g_bucket[NMAX * CAP];  // packed (src:17 | biased-q15 a_edge)
__device__ float    g_we[EDIM];            // W_edge @ att_edge
__device__ __align__(16) float g_ws[FIN];  // W @ att_src
__device__ __align__(16) float g_wd[FIN];  // W @ att_dst
__device__ int      g_idx64;               // 1 if edge_index is int64, 0 if int32

// ---------------- fused setup: zero cnt + dtype probe + weight precompute -----
__global__ void k_setup(const float* __restrict__ W, const float* __restrict__ We,
                        const float* __restrict__ as_, const float* __restrict__ ad_,
                        const float* __restrict__ ae_, const int* __restrict__ ei32, int n) {
    int i = blockIdx.x * 256 + threadIdx.x;
    if (i < n) g_cnt[i] = 0;
    if (blockIdx.x == 0) {
        // dtype probe: int64 edge_index has zero high words (first 8KB, in-bounds either way)
        int tid = threadIdx.x, nz = 0;
        #pragma unroll
        for (int j = 0; j < 4; j++) {
            int k = tid * 4 + j;                 // 0..1023
            if (ei32[2 * k + 1] != 0) nz = 1;
        }
        int any = __syncthreads_or(nz);
        if (tid == 0) g_idx64 = any ? 0 : 1;
    } else if (blockIdx.x == 1) {
        // precompute ws = W@att_src, wd = W@att_dst, we = We@att_e
        int w = threadIdx.x >> 5, lane = threadIdx.x & 31;   // 8 warps
        float ae0 = ae_[lane], ae1 = ae_[lane + 32];
        float as0 = as_[lane], as1 = as_[lane + 32];
        float ad0 = ad_[lane], ad1 = ad_[lane + 32];
        for (int r = w; r < FIN; r += 8) {
            float ps = W[r * H + lane] * as0 + W[r * H + lane + 32] * as1;
            float pd = W[r * H + lane] * ad0 + W[r * H + lane + 32] * ad1;
            #pragma unroll
            for (int o = 16; o; o >>= 1) {
                ps += __shfl_down_sync(0xffffffffu, ps, o);
                pd += __shfl_down_sync(0xffffffffu, pd, o);
            }
            if (!lane) { g_ws[r] = ps; g_wd[r] = pd; }
        }
        for (int r = w; r < EDIM; r += 8) {
            float p = We[r * H + lane] * ae0 + We[r * H + lane + 32] * ae1;
            #pragma unroll
            for (int o = 16; o; o >>= 1) p += __shfl_down_sync(0xffffffffu, p, o);
            if (!lane) g_we[r] = p;
        }
    }
}

// ------- fused main: edge blocks (a_edge + bucket scatter) || node blocks (h) --
#define EPB 512          // edges per edge-block (2 per thread)
#define NPW 16
__global__ __launch_bounds__(256) void k_main(
    const float* __restrict__ x, const float* __restrict__ W,
    const void* __restrict__ ei_raw, const float* __restrict__ ea,
    int n, int E, int edgeBlocks) {
    __shared__ float swe[EDIM];
    __shared__ __align__(16) float sea[EPB * EDIM];   // 16B-aligned for float4 staging
    if (blockIdx.x < edgeBlocks) {
        // ---- edge part: 2 edges/thread, a = ea @ w_e, one-atomic packed scatter
        int tid = threadIdx.x;
        if (tid < EDIM) swe[tid] = g_we[tid];
        long long base = (long long)blockIdx.x * EPB;
        long long astart = base * EDIM;
        long long total = (long long)E * EDIM;
        // astart*4 bytes = blockIdx*18432 -> 16B multiple when ea itself is 16B aligned
        if (astart + (long long)(EPB * EDIM) <= total &&
            ((((unsigned long long)ea) & 15ull) == 0ull)) {
            const float4* srcv = (const float4*)(ea + astart);
            float4* dstv = (float4*)sea;
            #pragma unroll
            for (int i = 0; i < (EPB * EDIM) / 4 / 256; i++)    // 4 iters
                dstv[tid + i * 256] = srcv[tid + i * 256];
            {   // remainder (1152 = 4*256 + 128)
                int i = (EPB * EDIM) / 4 / 256 * 256 + tid;
                if (i < (EPB * EDIM) / 4) dstv[i] = srcv[i];
            }
        } else {
            int acount = (int)min((long long)(EPB * EDIM), total - astart);
            for (int i = tid; i < acount; i += 256) sea[i] = ea[astart + i];
        }
        __syncthreads();
        int e0 = (int)base + tid;
        int e1 = e0 + 256;
        bool v0 = e0 < E, v1 = e1 < E;
        int s0 = 0, d0 = 0, s1 = 0, d1 = 0;
        if (g_idx64) {
            const long long* ei = (const long long*)ei_raw;
            if (v0) { s0 = (int)ei[e0]; d0 = (int)ei[E + e0]; }
            if (v1) { s1 = (int)ei[e1]; d1 = (int)ei[E + e1]; }
        } else {
            const int* ei = (const int*)ei_raw;
            if (v0) { s0 = ei[e0]; d0 = ei[E + e0]; }
            if (v1) { s1 = ei[e1]; d1 = ei[E + e1]; }
        }
        float a0 = 0.f, a1 = 0.f;
        #pragma unroll
        for (int k = 0; k < EDIM; k++) {
            a0 = fmaf(sea[tid * EDIM + k], swe[k], a0);
            a1 = fmaf(sea[(tid + 256) * EDIM + k], swe[k], a1);
        }
        int q0 = max(-16383, min(16383, __float2int_rn(a0 * QS)));
        int q1 = max(-16383, min(16383, __float2int_rn(a1 * QS)));
        // two independent atomic->store chains, interleaved for MLP
        int p0 = -1, p1 = -1;
        if (v0) p0 = atomicAdd(&g_cnt[d0], 1);
        if (v1) p1 = atomicAdd(&g_cnt[d1], 1);
        if (v0 && p0 < CAP)
            g_bucket[d0 * CAP + p0] = ((unsigned)s0 << 15) | (unsigned)(q0 + 16384);
        if (v1 && p1 < CAP)
            g_bucket[d1 * CAP + p1] = ((unsigned)s1 << 15) | (unsigned)(q1 + 16384);
    } else {
        // ---- node part: h = x@W (half2), a_src, a_dst ----
        int bid = blockIdx.x - edgeBlocks;
        int gw = bid * 8 + (threadIdx.x >> 5);
        int lane = threadIdx.x & 31;
        int base0 = gw * NPW;
        if (base0 >= n) return;
        float w0[FIN], w1[FIN];
        #pragma unroll
        for (int k = 0; k < FIN; k++) {
            float2 wv = ((const float2*)(W + k * H))[lane];
            w0[k] = wv.x; w1[k] = wv.y;
        }
        float4 ws4 = ((const float4*)g_ws)[lane & 3];
        float4 wd4 = ((const float4*)g_wd)[lane & 3];
        for (int b = 0; b < NPW; b += 8) {
            int base = base0 + b;
            if (base >= n) break;
            int mynode = base + (lane >> 2);
            float4 x4 = make_float4(0.f, 0.f, 0.f, 0.f);
            if (mynode < n) x4 = ((const float4*)x)[base * 4 + lane];
            float rs = x4.x * ws4.x + x4.y * ws4.y + x4.z * ws4.z + x4.w * ws4.w;
            float rd = x4.x * wd4.x + x4.y * wd4.y + x4.z * wd4.z + x4.w * wd4.w;
            rs += __shfl_xor_sync(0xffffffffu, rs, 1);
            rd += __shfl_xor_sync(0xffffffffu, rd, 1);
            rs += __shfl_xor_sync(0xffffffffu, rs, 2);
            rd += __shfl_xor_sync(0xffffffffu, rd, 2);
            if ((lane & 3) == 0 && mynode < n) { g_asrc[mynode] = rs; g_adst[mynode] = rd; }
            #pragma unroll
            for (int i = 0; i < 8; i++) {
                int node = base + i;
                if (node >= n) break;              // uniform across warp
                float a0 = 0.f, a1 = 0.f;
                #pragma unroll
                for (int k = 0; k < FIN; k++) {
                    float xc = ((k & 3) == 0) ? x4.x : ((k & 3) == 1) ? x4.y
                             : ((k & 3) == 2) ? x4.z : x4.w;
                    float xk = __shfl_sync(0xffffffffu, xc, (i << 2) + (k >> 2));
                    a0 = fmaf(xk, w0[k], a0);
                    a1 = fmaf(xk, w1[k], a1);
                }
                g_h2[node * 32 + lane] = __floats2half2_rn(a0, a1);
            }
        }
    }
}

// ------- per node warp: softmax + aggregate + relu + @lin_w (single pass) -----
__global__ void k_aggregate(const float* __restrict__ bias, const float* __restrict__ lin_w, int n) {
    int warp = threadIdx.x >> 5, lane = threadIdx.x & 31;
    int node = blockIdx.x * (blockDim.x >> 5) + warp;
    if (node >= n) return;
    int deg = g_cnt[node];
    int cnt = min(deg, CAP);
    float adst_n = g_adst[node];

    const unsigned* bkt = &g_bucket[node * CAP];
    float acc0 = 0.f, acc1 = 0.f;
    float asum = 0.f, dsum = 0.f;

    for (int i0 = 0; i0 < cnt; i0 += 32) {
        bool valid = (i0 + lane) < cnt;
        unsigned w = bkt[valid ? (i0 + lane) : 0];       // coalesced 128B per warp
        int src = (int)(w >> 15);
        float a_l = ((int)(w & 0x7FFFu) - 16384) * (1.f / QS);
        float asrc_s = __ldg(&g_asrc[src]);              // lane-parallel random gather
        float alf = asrc_s + adst_n + a_l;
        alf = (alf >= 0.f) ? alf : 0.2f * alf;           // leaky_relu(0.2)
        float ex = valid ? __expf(alf) : 0.f;
        asum += valid ? a_l : 0.f;
        dsum += ex;
        int m = min(cnt - i0, 32);
        #pragma unroll 4
        for (int j = 0; j < m; j++) {
            unsigned wj = __shfl_sync(0xffffffffu, w, j);
            float exj = __shfl_sync(0xffffffffu, ex, j);
            int sj = (int)(wj >> 15);
            float2 hf = __half22float2(g_h2[sj * 32 + lane]);
            acc0 = fmaf(exj, hf.x, acc0);
            acc1 = fmaf(exj, hf.y, acc1);
        }
    }
    #pragma unroll
    for (int o = 16; o; o >>= 1) {
        asum += __shfl_xor_sync(0xffffffffu, asum, o);
        dsum += __shfl_xor_sync(0xffffffffu, dsum, o);
    }
    // self loop: alpha = a_src + a_dst + mean(a_edge over incoming)
    float al = g_asrc[node] + adst_n + asum / fmaxf((float)deg, 1.f);
    al = (al >= 0.f) ? al : 0.2f * al;
    float exl = __expf(al);
    {
        float2 hf = __half22float2(g_h2[node * 32 + lane]);
        acc0 = fmaf(exl, hf.x, acc0);
        acc1 = fmaf(exl, hf.y, acc1);
    }
    float inv = 1.f / (dsum + exl + 1e-16f);
    float v0 = fmaxf(acc0 * inv + __ldg(&bias[2 * lane]),     0.f);
    float v1 = fmaxf(acc1 * inv + __ldg(&bias[2 * lane + 1]), 0.f);
    float yp = v0 * __ldg(&lin_w[2 * lane]) + v1 * __ldg(&lin_w[2 * lane + 1]);
    #pragma unroll
    for (int o = 16; o; o >>= 1) yp += __shfl_down_sync(0xffffffffu, yp, o);
    if (!lane) g_y[node] = yp;
}

// ---------------- per edge readout: 4 edges/thread, batched gathers -----------
#define OUT_Q 4
__global__ __launch_bounds__(512) void k_out(
    const void* __restrict__ ei_raw, float* __restrict__ out,
    const float* __restrict__ lin_b, int E, int stride) {
    int gid = blockIdx.x * 512 + threadIdx.x;
    float lb = __ldg(&lin_b[0]);
    int s[OUT_Q], d[OUT_Q];
    bool v[OUT_Q];
    // phase 1: coalesced index loads (independent)
    if (g_idx64) {
        const long long* ei = (const long long*)ei_raw;
        #pragma unroll
        for (int j = 0; j < OUT_Q; j++) {
            int e = gid + j * stride;
            v[j] = e < E;
            s[j] = v[j] ? (int)ei[e] : 0;
            d[j] = v[j] ? (int)ei[E + e] : 0;
        }
    } else {
        const int* ei = (const int*)ei_raw;
        #pragma unroll
        for (int j = 0; j < OUT_Q; j++) {
            int e = gid + j * stride;
            v[j] = e < E;
            s[j] = v[j] ? ei[e] : 0;
            d[j] = v[j] ? ei[E + e] : 0;
        }
    }
    // phase 2: independent random gathers in flight
    float ys[OUT_Q], yd[OUT_Q];
    #pragma unroll
    for (int j = 0; j < OUT_Q; j++) {
        ys[j] = __ldg(&g_y[s[j]]);
        yd[j] = __ldg(&g_y[d[j]]);
    }
    // phase 3: compute + coalesced stores
    #pragma unroll
    for (int j = 0; j < OUT_Q; j++) {
        if (v[j]) {
            float z = 0.5f * (ys[j] + yd[j]) + lb;
            out[gid + j * stride] = 1.f / (1.f + __expf(-z));
        }
    }
}

// ---------------- launch -------------------------------------------------------
extern "C" void kernel_launch(void* const* d_in, const int* in_sizes, int n_in,
                              void* d_out, int out_size) {
    const float* x       = (const float*)d_in[0];
    const float* ea      = (const float*)d_in[1];
    const float* W       = (const float*)d_in[2];
    const float* We      = (const float*)d_in[3];
    const float* att_src = (const float*)d_in[4];
    const float* att_dst = (const float*)d_in[5];
    const float* att_e   = (const float*)d_in[6];
    const float* bias    = (const float*)d_in[7];
    const float* lin_w   = (const float*)d_in[8];
    const float* lin_b   = (const float*)d_in[9];
    const void*  ei      = (const void*)d_in[10];

    int n = in_sizes[0] / FIN;       // 100000
    int E = in_sizes[10] / 2;        // 1600000 (element count, dtype-independent)

    k_setup<<<(n + 255) / 256, 256>>>(W, We, att_src, att_dst, att_e, (const int*)ei, n);

    int edgeBlocks = (E + EPB - 1) / EPB;                 // 3125
    int nodeBlocks = ((n + NPW - 1) / NPW + 7) / 8;       // 782
    k_main<<<edgeBlocks + nodeBlocks, 256>>>(x, W, ei, ea, n, E, edgeBlocks);

    k_aggregate<<<(n + 7) / 8, 256>>>(bias, lin_w, n);

    int outBlocks = (E + 512 * OUT_Q - 1) / (512 * OUT_Q);  // 782
    int stride = outBlocks * 512;
    k_out<<<outBlocks, 512>>>(ei, (float*)d_out, lin_b, E, stride);
}